// round 15
// baseline (speedup 1.0000x reference)
#include <cuda_runtime.h>
#include <cuda_bf16.h>
#include <math.h>
#include <stdint.h>

// ---------------- problem constants ----------------
#define Bn   16
#define Hn   56
#define Wn   56
#define Cn   256
#define NPIX (Bn*Hn*Wn)        // 50176 tokens
#define NHn  8
#define HDn  32
#define Ln   49
#define NWIN 1024
#define QS   (NWIN*NHn*Ln*HDn)
#define HIDn 1024

// weight buffer offsets (bf16 elems)
#define W_QKV  0
#define W_PROJ 196608
#define W_FC1  262144
#define W_FC2  524288
#define W_TOT  786432

// GEMM smem: 3 stages x 128 rows x 20 u32, A + B  (dynamic)
#define GSTG   (128*20)            // u32 per stage per matrix
#define NSTAGE 3
#define GSMEM_BYTES (NSTAGE*GSTG*2*4)   // 61440

// bias table: padded rows of 52 floats for aligned float2 reads
#define BROW 52

// ---------------- scratch ----------------
__device__ __nv_bfloat16 g_wh [W_TOT];
__device__ float         g_xa [NPIX*Cn];
__device__ __nv_bfloat16 g_ln1h[NPIX*Cn];
__device__ __nv_bfloat16 g_qkh[2*QS];              // q,k
__device__ uint32_t      g_vth[8192*1536];         // V^T bf16 slab layout, zero-init padding
__device__ __nv_bfloat16 g_atth[NPIX*Cn];
__device__ float         g_x2 [NPIX*Cn];
__device__ __nv_bfloat16 g_ln2h[NPIX*Cn];
__device__ __nv_bfloat16 g_mlph[NPIX*HIDn];
__device__ float g_bias[NHn*Ln*BROW + 16];         // padded, +16 guard for f2 tail

// ---------------- helpers ----------------
__device__ __forceinline__ int token_pixel(int t) {
    int win = t / Ln, l = t - win * Ln;
    int b  = win >> 6, wi = win & 63;
    int hr = (wi >> 3) * 7 + l / 7 + 3; if (hr >= 56) hr -= 56;
    int wr = (wi & 7)  * 7 + (l % 7) + 3; if (wr >= 56) wr -= 56;
    return (b * 56 + hr) * 56 + wr;
}

__device__ __forceinline__ uint32_t pack_bf16(float lo, float hi) {
    uint32_t u;
    asm("cvt.rn.bf16x2.f32 %0, %1, %2;" : "=r"(u) : "f"(hi), "f"(lo));
    return u;
}

__device__ __forceinline__ float gelu_exact(float v) {
    return 0.5f * v * (1.0f + erff(v * 0.7071067811865475f));
}

__device__ __forceinline__ void mma_bf16(float4& d, const uint32_t a[4], const uint32_t b[2]) {
    asm volatile(
        "mma.sync.aligned.m16n8k16.row.col.f32.bf16.bf16.f32 "
        "{%0,%1,%2,%3}, {%4,%5,%6,%7}, {%8,%9}, {%0,%1,%2,%3};\n"
        : "+f"(d.x), "+f"(d.y), "+f"(d.z), "+f"(d.w)
        : "r"(a[0]), "r"(a[1]), "r"(a[2]), "r"(a[3]), "r"(b[0]), "r"(b[1]));
}

__device__ __forceinline__ void ldmx4(uint32_t r[4], uint32_t addr) {
    asm volatile("ldmatrix.sync.aligned.m8n8.x4.shared.b16 {%0,%1,%2,%3}, [%4];"
        : "=r"(r[0]), "=r"(r[1]), "=r"(r[2]), "=r"(r[3]) : "r"(addr));
}

#define CP16(dst, src) \
    asm volatile("cp.async.cg.shared.global [%0], [%1], 16;" :: "r"(dst), "l"(src))
#define CP_COMMIT() asm volatile("cp.async.commit_group;")
#define CP_WAITG1() asm volatile("cp.async.wait_group 1;" ::: "memory")

__device__ __forceinline__ float warp_sum(float v) {
    #pragma unroll
    for (int o = 16; o > 0; o >>= 1) v += __shfl_xor_sync(0xffffffffu, v, o);
    return v;
}

// ---------------- weight conversion ----------------
__global__ void convert_w_kernel(const float* __restrict__ qkv,
                                 const float* __restrict__ proj,
                                 const float* __restrict__ fc1,
                                 const float* __restrict__ fc2) {
    int i = blockIdx.x * blockDim.x + threadIdx.x;
    if (i >= W_TOT) return;
    float v;
    if      (i < W_PROJ) v = qkv [i - W_QKV];
    else if (i < W_FC1)  v = proj[i - W_PROJ];
    else if (i < W_FC2)  v = fc1 [i - W_FC1];
    else                 v = fc2 [i - W_FC2];
    g_wh[i] = __float2bfloat16(v);
}

// ---------------- setup: bias table (padded rows of BROW) ----------------
__global__ void setup_bias_kernel(const float* __restrict__ rpb1_w,
                                  const float* __restrict__ rpb1_b,
                                  const float* __restrict__ rpb2_w,
                                  const float* __restrict__ rpb2_b) {
    __shared__ float table[169 * 8];
    int tid = threadIdx.x;
    if (tid < 169) {
        int a = tid / 13, b2 = tid % 13;
        float dy = (float)(a - 6), dx = (float)(b2 - 6);
        float r0 = (dy > 0.f ? 1.f : (dy < 0.f ? -1.f : 0.f)) * log1pf(fabsf(dy));
        float r1 = (dx > 0.f ? 1.f : (dx < 0.f ? -1.f : 0.f)) * log1pf(fabsf(dx));
        float acc[8] = {0,0,0,0,0,0,0,0};
        for (int j = 0; j < 512; j++) {
            float hj = fmaxf(0.f, r0 * rpb1_w[2*j] + r1 * rpb1_w[2*j+1] + rpb1_b[j]);
            #pragma unroll
            for (int h = 0; h < 8; h++) acc[h] += hj * rpb2_w[h*512 + j];
        }
        #pragma unroll
        for (int h = 0; h < 8; h++) table[tid*8 + h] = acc[h] + rpb2_b[h];
    }
    __syncthreads();
    for (int e = tid; e < NHn*Ln*Ln; e += blockDim.x) {
        int h = e / (Ln*Ln), r = e % (Ln*Ln), i = r / Ln, j = r % Ln;
        int idx = (i/7 - j/7 + 6) * 13 + (i%7 - j%7 + 6);
        g_bias[(h*Ln + i)*BROW + j] = table[idx*8 + h];
    }
}

__device__ __forceinline__ int shift_label(int t) { return t < 49 ? 0 : (t < 53 ? 1 : 2); }

// ---------------- K1: APE conv + residual + LN1 (row-walking) -------------
__global__ void __launch_bounds__(256)
ape_ln_kernel(const float* __restrict__ x,  const float* __restrict__ apw,
              const float* __restrict__ apb, const float* __restrict__ nw,
              const float* __restrict__ nb) {
    __shared__ float red[2][8];
    int c = threadIdx.x;
    int bh = blockIdx.x;
    int h = bh % 56;
    bool hm = h > 0, hp = h < 55;

    const float* r1 = x + (size_t)bh*56*Cn + c;
    const float* r0 = r1 - 56*Cn;
    const float* r2 = r1 + 56*Cn;

    float w9[9];
    #pragma unroll
    for (int i = 0; i < 9; i++) w9[i] = apw[i*Cn + c];
    float bias = apb[c], nwc = nw[c], nbc = nb[c];

    float a0=0.f, a1=0.f, a2=0.f;
    float b0, b1, b2, c0, c1, c2;
    b0 = hm ? r0[0] : 0.f;  b1 = r1[0];  b2 = hp ? r2[0] : 0.f;
    c0 = hm ? r0[Cn] : 0.f; c1 = r1[Cn]; c2 = hp ? r2[Cn] : 0.f;

    int lane = c & 31, wid = c >> 5;
    for (int w = 0; w < 56; w++) {
        float v = b1 + bias
                + a0*w9[0] + b0*w9[1] + c0*w9[2]
                + a1*w9[3] + b1*w9[4] + c1*w9[5]
                + a2*w9[6] + b2*w9[7] + c2*w9[8];

        float n0 = 0.f, n1 = 0.f, n2 = 0.f;
        if (w + 2 < 56) {
            size_t off = (size_t)(w+2)*Cn;
            n0 = hm ? r0[off] : 0.f; n1 = r1[off]; n2 = hp ? r2[off] : 0.f;
        }

        float s = warp_sum(v), sq = warp_sum(v*v);
        if (lane == 0) { red[0][wid] = s; red[1][wid] = sq; }
        __syncthreads();
        float S = 0.f, SQ = 0.f;
        #pragma unroll
        for (int i = 0; i < 8; i++) { S += red[0][i]; SQ += red[1][i]; }
        __syncthreads();
        float mean = S * (1.0f/256.0f);
        float var  = SQ * (1.0f/256.0f) - mean*mean;
        float rstd = rsqrtf(var + 1e-5f);

        size_t idx = ((size_t)bh*56 + w)*Cn + c;
        g_xa[idx]   = v;
        g_ln1h[idx] = __float2bfloat16((v - mean) * rstd * nwc + nbc);

        a0 = b0; a1 = b1; a2 = b2;
        b0 = c0; b1 = c1; b2 = c2;
        c0 = n0; c1 = n1; c2 = n2;
    }
}

// ---------------- LN2 (warp per pixel) ----------------
__global__ void __launch_bounds__(256)
ln2_kernel(const float* __restrict__ nw, const float* __restrict__ nb) {
    int wpb = threadIdx.x >> 5, lane = threadIdx.x & 31;
    int p = blockIdx.x * 8 + wpb;
    int c0 = lane * 8;
    size_t idx = (size_t)p*Cn + c0;
    float4 s0 = *(const float4*)(g_x2 + idx), s1 = *(const float4*)(g_x2 + idx + 4);
    float v[8] = {s0.x,s0.y,s0.z,s0.w,s1.x,s1.y,s1.z,s1.w};
    float s = 0.f;
    #pragma unroll
    for (int i = 0; i < 8; i++) s += v[i];
    float mean = warp_sum(s) * (1.0f/256.0f);
    float d[8], sq = 0.f;
    #pragma unroll
    for (int i = 0; i < 8; i++) { d[i] = v[i] - mean; sq += d[i]*d[i]; }
    float rstd = rsqrtf(warp_sum(sq) * (1.0f/256.0f) + 1e-5f);
    float4 nwv0 = *(const float4*)(nw + c0), nwv1 = *(const float4*)(nw + c0 + 4);
    float4 nbv0 = *(const float4*)(nb + c0), nbv1 = *(const float4*)(nb + c0 + 4);
    float o[8];
    o[0]=d[0]*rstd*nwv0.x+nbv0.x; o[1]=d[1]*rstd*nwv0.y+nbv0.y;
    o[2]=d[2]*rstd*nwv0.z+nbv0.z; o[3]=d[3]*rstd*nwv0.w+nbv0.w;
    o[4]=d[4]*rstd*nwv1.x+nbv1.x; o[5]=d[5]*rstd*nwv1.y+nbv1.y;
    o[6]=d[6]*rstd*nwv1.z+nbv1.z; o[7]=d[7]*rstd*nwv1.w+nbv1.w;
    uint4 pk = make_uint4(pack_bf16(o[0],o[1]), pack_bf16(o[2],o[3]),
                          pack_bf16(o[4],o[5]), pack_bf16(o[6],o[7]));
    *(uint4*)(g_ln2h + idx) = pk;
}

// ---------------- bf16 TC GEMM, k-slab 32, 3-stage cp.async ---------------
template<int EPI, int KSIZE>
__global__ void __launch_bounds__(256, 2)
gemm_tc(int woff, const float* __restrict__ bvec, float* __restrict__ outp) {
    const __nv_bfloat16* A = (EPI == 0) ? g_ln1h : (EPI == 1) ? g_atth
                           : (EPI == 2) ? g_ln2h : g_mlph;
    const __nv_bfloat16* W = g_wh + woff;

    extern __shared__ __align__(16) uint32_t dsm[];
    uint32_t* Asm = dsm;                 // [3][128][20]
    uint32_t* Bsm = dsm + 3*GSTG;        // [3][128][20]
    __shared__ const __nv_bfloat16* rowp[128];

    int tid = threadIdx.x;
    int m0 = blockIdx.x * 128, n0 = blockIdx.y * 128;
    if (tid < 128) {
        int t = m0 + tid;
        rowp[tid] = (EPI == 0) ? (A + (size_t)token_pixel(t)*KSIZE)
                               : (A + (size_t)t*KSIZE);
    }
    __syncthreads();

    int lm = tid >> 1;
    int half = tid & 1;
    const __nv_bfloat16* Asrc = rowp[lm] + half*16;
    const __nv_bfloat16* Bsrc = W + (size_t)(n0 + lm) * KSIZE + half*16;

    uint32_t sA = (uint32_t)__cvta_generic_to_shared(Asm + lm*20 + half*8);
    uint32_t sB = (uint32_t)__cvta_generic_to_shared(Bsm + lm*20 + half*8);
    const int STG = GSTG*4;              // 10240 bytes per stage

    int wid = tid >> 5, lane = tid & 31;
    int wm = wid >> 2, wn = wid & 3;
    int g = lane >> 2, t4 = lane & 3;

    uint32_t a_row  = (uint32_t)(wm*64 + (lane & 15));
    uint32_t a_koff = (uint32_t)((lane >> 4) * 4);
    uint32_t b_row0 = (uint32_t)(wn*32 + ((lane >> 4) ? 8 : 0) + (lane & 7));
    uint32_t b_koff = (uint32_t)(((lane >> 3) & 1) * 4);
    uint32_t aBase = (uint32_t)__cvta_generic_to_shared(Asm + a_row*20 + a_koff);
    uint32_t bBase = (uint32_t)__cvta_generic_to_shared(Bsm + b_row0*20 + b_koff);

    float4 acc[4][4];
    #pragma unroll
    for (int i = 0; i < 4; i++)
        #pragma unroll
        for (int j = 0; j < 4; j++) acc[i][j] = make_float4(0.f,0.f,0.f,0.f);

    const int NSLAB = KSIZE / 32;
    CP16(sA, Asrc);        CP16(sA + 16, Asrc + 8);
    CP16(sB, Bsrc);        CP16(sB + 16, Bsrc + 8);         CP_COMMIT();
    CP16(sA + STG, Asrc + 32); CP16(sA + STG + 16, Asrc + 40);
    CP16(sB + STG, Bsrc + 32); CP16(sB + STG + 16, Bsrc + 40); CP_COMMIT();

    int buf = 0;
    for (int i = 0; i < NSLAB; i++) {
        CP_WAITG1();
        __syncthreads();
        int ip = i + 2;
        if (ip < NSLAB) {
            int pb = ip % 3;
            const __nv_bfloat16* as = Asrc + ip*32;
            const __nv_bfloat16* bs = Bsrc + ip*32;
            CP16(sA + pb*STG, as);      CP16(sA + pb*STG + 16, as + 8);
            CP16(sB + pb*STG, bs);      CP16(sB + pb*STG + 16, bs + 8);
        }
        CP_COMMIT();

        uint32_t ab = aBase + buf*STG;
        uint32_t bb = bBase + buf*STG;
        #pragma unroll
        for (int kh = 0; kh < 2; kh++) {
            uint32_t afr[4][4], bfr[2][4];
            #pragma unroll
            for (int mt = 0; mt < 4; mt++) ldmx4(afr[mt], ab + mt*1280 + kh*32);
            #pragma unroll
            for (int np = 0; np < 2; np++) ldmx4(bfr[np], bb + np*1280 + kh*32);
            #pragma unroll
            for (int mt = 0; mt < 4; mt++) {
                #pragma unroll
                for (int np = 0; np < 2; np++) {
                    mma_bf16(acc[mt][2*np  ], afr[mt], &bfr[np][0]);
                    mma_bf16(acc[mt][2*np+1], afr[mt], &bfr[np][2]);
                }
            }
        }
        buf = (buf == 2) ? 0 : buf + 1;
    }

    // ---------------- vectorized epilogues ----------------
    #pragma unroll
    for (int mt = 0; mt < 4; mt++) {
        int rbase = m0 + wm*64 + mt*16 + g;
        #pragma unroll
        for (int rr = 0; rr < 2; rr++) {
            int r = rbase + rr*8;
            int pix = 0, win = 0, l = 0;
            if (EPI == 0) { win = r / Ln; l = r - win*Ln; }
            if (EPI == 1) pix = token_pixel(r);
            #pragma unroll
            for (int nt = 0; nt < 4; nt++) {
                int c0 = n0 + wn*32 + nt*8 + 2*t4;   // even
                float v0 = (rr == 0 ? acc[mt][nt].x : acc[mt][nt].z);
                float v1 = (rr == 0 ? acc[mt][nt].y : acc[mt][nt].w);
                float val0 = v0 + bvec[c0];
                float val1 = v1 + bvec[c0 + 1];
                if (EPI == 0) {
                    int which = c0 >> 8, head = (c0 >> 5) & 7, hd = c0 & 31;
                    if (which < 2) {
                        size_t idx = (((size_t)(win<<3) + head)*Ln + l)*HDn + hd;
                        *(uint32_t*)&g_qkh[(size_t)which*QS + idx] = pack_bf16(val0, val1);
                    } else {
                        int slab = l >> 4;
                        __nv_bfloat16* vb = (__nv_bfloat16*)g_vth
                            + (size_t)((win<<3)+head)*3072 + (l & 15);
                        vb[(slab*32 + hd    )*24] = __float2bfloat16(val0);
                        vb[(slab*32 + hd + 1)*24] = __float2bfloat16(val1);
                    }
                } else if (EPI == 1) {
                    size_t idx = (size_t)pix*Cn + c0;
                    float2 xa = *(const float2*)&g_xa[idx];
                    *(float2*)&g_x2[idx] = make_float2(xa.x + val0, xa.y + val1);
                } else if (EPI == 2) {
                    *(uint32_t*)&g_mlph[(size_t)r*HIDn + c0] =
                        pack_bf16(gelu_exact(val0), gelu_exact(val1));
                } else {
                    size_t idx = (size_t)r*Cn + c0;
                    float2 x2 = *(const float2*)&g_x2[idx];
                    *(float2*)&outp[idx] = make_float2(x2.x + val0, x2.y + val1);
                }
            }
        }
    }
}

// ---------------- attention: raw-S MMA + deferred cosine norm -------------
// Loader is a pure uint4 copy of q,k into slabs; row inverse-norms go to
// qn/kn smem.  Softmax applies acc*(tsc*qn[i])*kn[j] in fp32.
__global__ void __launch_bounds__(128)
attn_kernel(const float* __restrict__ scale) {
    int win = blockIdx.x, head = blockIdx.y;
    int wh = win*NHn + head;
    __shared__ __align__(16) uint32_t qs[2][64][12];
    __shared__ __align__(16) uint32_t ks[2][64][12];
    __shared__ __align__(16) uint32_t ps[4][64][12];
    __shared__ __align__(16) uint32_t vt[4][32][12];
    __shared__ float qn[64], kn[64];

    int tid = threadIdx.x, lane = tid & 31, w = tid >> 5;

    // ---- copy q,k rows raw + compute inverse norms ----
    {
        const __nv_bfloat16* qg = g_qkh + (size_t)wh*Ln*HDn;
        bool isq = tid < 64;
        int r = isq ? tid : tid - 64;
        uint32_t (*dst)[12] = isq ? qs[0] : ks[0];
        float* nrm = isq ? qn : kn;
        if (r < Ln) {
            const __nv_bfloat16* src = (isq ? qg : qg + QS) + r*HDn;
            uint4 u0 = *(const uint4*)(src);
            uint4 u1 = *(const uint4*)(src + 8);
            uint4 u2 = *(const uint4*)(src + 16);
            uint4 u3 = *(const uint4*)(src + 24);
            *(uint4*)&dst[r][0] = u0;      *(uint4*)&dst[r][4] = u1;
            *(uint4*)&dst[64 + r][0] = u2; *(uint4*)&dst[64 + r][4] = u3;
            uint32_t uu[16] = {u0.x,u0.y,u0.z,u0.w, u1.x,u1.y,u1.z,u1.w,
                               u2.x,u2.y,u2.z,u2.w, u3.x,u3.y,u3.z,u3.w};
            float ssum = 0.f;
            #pragma unroll
            for (int i = 0; i < 16; i++) {
                __nv_bfloat162 b2 = *(__nv_bfloat162*)&uu[i];
                float fx = __bfloat162float(b2.x), fy = __bfloat162float(b2.y);
                ssum += fx*fx + fy*fy;
            }
            nrm[r] = 1.0f / fmaxf(sqrtf(ssum), 1e-12f);
        } else {
            uint4 z = make_uint4(0,0,0,0);
            *(uint4*)&dst[r][0] = z; *(uint4*)&dst[r][4] = z;
            *(uint4*)&dst[64 + r][0] = z; *(uint4*)&dst[64 + r][4] = z;
            nrm[r] = 0.f;
        }
    }
    // ---- copy V^T slabs ----
    {
        const uint4* vsrc = (const uint4*)(g_vth + (size_t)wh*1536);
        uint4* vdst = (uint4*)vt;
        #pragma unroll
        for (int i = 0; i < 3; i++) vdst[tid + i*128] = vsrc[tid + i*128];
    }
    __syncthreads();

    int g = lane >> 2, t4 = lane & 3;
    uint32_t aBase = (uint32_t)__cvta_generic_to_shared(&qs[0][w*16 + (lane&15)][(lane>>4)*4]);
    uint32_t bBase = (uint32_t)__cvta_generic_to_shared(
        &ks[0][((lane>>4) ? 8 : 0) + (lane&7)][((lane>>3)&1)*4]);

    // ---- S = q . k^T (raw, acc in registers) ----
    float4 acc[8];
    #pragma unroll
    for (int i = 0; i < 8; i++) acc[i] = make_float4(0.f,0.f,0.f,0.f);
    #pragma unroll
    for (int s = 0; s < 2; s++) {
        uint32_t afr[4], bfr[4][4];
        ldmx4(afr, aBase + s*64*48);
        #pragma unroll
        for (int np = 0; np < 4; np++) ldmx4(bfr[np], bBase + s*64*48 + np*16*48);
        #pragma unroll
        for (int np = 0; np < 4; np++) {
            mma_bf16(acc[2*np  ], afr, &bfr[np][0]);
            mma_bf16(acc[2*np+1], afr, &bfr[np][2]);
        }
    }

    // ---- in-register softmax with deferred normalization ----
    {
        float tsc = __expf(-scale[head]);
        int w63 = win & 63;
        int whh = w63 >> 3, www = w63 & 7;
        int i1 = w*16 + g, i2 = i1 + 8;
        bool v1r = i1 < Ln, v2r = i2 < Ln;
        int ci1 = v1r ? shift_label(whh*7 + i1/7)*3 + shift_label(www*7 + i1%7) : 0;
        int ci2 = v2r ? shift_label(whh*7 + i2/7)*3 + shift_label(www*7 + i2%7) : 0;
        float sc1 = v1r ? tsc * qn[i1] : 0.f;
        float sc2 = v2r ? tsc * qn[i2] : 0.f;
        const float2* b1v = (const float2*)(g_bias + ((size_t)head*Ln + (v1r ? i1 : 0))*BROW);
        const float2* b2v = (const float2*)(g_bias + ((size_t)head*Ln + (v2r ? i2 : 0))*BROW);
        const float2* knv = (const float2*)kn;

        float x1[16], x2[16];
        #pragma unroll
        for (int nt = 0; nt < 8; nt++) {
            int c = nt*8 + 2*t4;
            float2 bb1 = b1v[nt*4 + t4];
            float2 bb2 = b2v[nt*4 + t4];
            float2 kk  = knv[nt*4 + t4];
            #pragma unroll
            for (int jj = 0; jj < 2; jj++) {
                int j = c + jj;
                float va = (jj == 0 ? acc[nt].x : acc[nt].y);
                float vb = (jj == 0 ? acc[nt].z : acc[nt].w);
                float bj1 = (jj == 0 ? bb1.x : bb1.y);
                float bj2 = (jj == 0 ? bb2.x : bb2.y);
                float kj  = (jj == 0 ? kk.x  : kk.y);
                if (j < Ln) {
                    int cj = shift_label(whh*7 + j/7)*3 + shift_label(www*7 + j%7);
                    x1[nt*2+jj] = v1r ? va*sc1*kj + bj1 + ((cj != ci1) ? -100.f : 0.f) : -1e30f;
                    x2[nt*2+jj] = v2r ? vb*sc2*kj + bj2 + ((cj != ci2) ? -100.f : 0.f) : -1e30f;
                } else {
                    x1[nt*2+jj] = -1e30f;
                    x2[nt*2+jj] = -1e30f;
                }
            }
        }
        float m1 = -1e30f, m2 = -1e30f;
        #pragma unroll
        for (int k = 0; k < 16; k++) { m1 = fmaxf(m1, x1[k]); m2 = fmaxf(m2, x2[k]); }
        m1 = fmaxf(m1, __shfl_xor_sync(0xffffffffu, m1, 1));
        m1 = fmaxf(m1, __shfl_xor_sync(0xffffffffu, m1, 2));
        m2 = fmaxf(m2, __shfl_xor_sync(0xffffffffu, m2, 1));
        m2 = fmaxf(m2, __shfl_xor_sync(0xffffffffu, m2, 2));
        float s1 = 0.f, s2 = 0.f;
        #pragma unroll
        for (int k = 0; k < 16; k++) {
            x1[k] = __expf(x1[k] - m1); s1 += x1[k];
            x2[k] = __expf(x2[k] - m2); s2 += x2[k];
        }
        s1 += __shfl_xor_sync(0xffffffffu, s1, 1);
        s1 += __shfl_xor_sync(0xffffffffu, s1, 2);
        s2 += __shfl_xor_sync(0xffffffffu, s2, 1);
        s2 += __shfl_xor_sync(0xffffffffu, s2, 2);
        float inv1 = 1.0f / s1, inv2 = 1.0f / s2;

        uint32_t* pf = (uint32_t*)ps;
        #pragma unroll
        for (int nt = 0; nt < 8; nt++) {
            int c = nt*8 + 2*t4;
            int sb = (c >> 4), cc = (c & 15) >> 1;
            pf[(sb*64 + i1)*12 + cc] = pack_bf16(x1[2*nt]*inv1, x1[2*nt+1]*inv1);
            pf[(sb*64 + i2)*12 + cc] = pack_bf16(x2[2*nt]*inv2, x2[2*nt+1]*inv2);
        }
    }
    __syncthreads();

    // ---- out = P . V ----
    {
        uint32_t pBase = (uint32_t)__cvta_generic_to_shared(
            &ps[0][w*16 + (lane&15)][(lane>>4)*4]);
        uint32_t vBase = (uint32_t)__cvta_generic_to_shared(
            &vt[0][((lane>>4) ? 8 : 0) + (lane&7)][((lane>>3)&1)*4]);
        float4 o[4];
        #pragma unroll
        for (int i = 0; i < 4; i++) o[i] = make_float4(0.f,0.f,0.f,0.f);
        #pragma unroll
        for (int s = 0; s < 4; s++) {
            uint32_t afr[4], bfr[2][4];
            ldmx4(afr, pBase + s*64*48);
            #pragma unroll
            for (int np = 0; np < 2; np++) ldmx4(bfr[np], vBase + s*32*48 + np*16*48);
            mma_bf16(o[0], afr, &bfr[0][0]);
            mma_bf16(o[1], afr, &bfr[0][2]);
            mma_bf16(o[2], afr, &bfr[1][0]);
            mma_bf16(o[3], afr, &bfr[1][2]);
        }
        __nv_bfloat16* ob = g_atth + ((size_t)win*Ln)*Cn + head*HDn;
        int i0 = w*16 + g;
        #pragma unroll
        for (int nt = 0; nt < 4; nt++) {
            int c = nt*8 + 2*t4;   // even
            if (i0 < Ln)
                *(uint32_t*)&ob[i0*Cn + c] = pack_bf16(o[nt].x, o[nt].y);
            if (i0 + 8 < Ln)
                *(uint32_t*)&ob[(i0+8)*Cn + c] = pack_bf16(o[nt].z, o[nt].w);
        }
    }
}

// ---------------- launch ----------------
extern "C" void kernel_launch(void* const* d_in, const int* in_sizes, int n_in,
                              void* d_out, int out_size) {
    const float* x       = (const float*)d_in[0];
    const float* ape_w   = (const float*)d_in[1];
    const float* ape_b   = (const float*)d_in[2];
    const float* norm1_w = (const float*)d_in[3];
    const float* norm1_b = (const float*)d_in[4];
    const float* qkv_w   = (const float*)d_in[5];
    const float* qkv_b   = (const float*)d_in[6];
    const float* scale   = (const float*)d_in[7];
    const float* rpb1_w  = (const float*)d_in[8];
    const float* rpb1_b  = (const float*)d_in[9];
    const float* rpb2_w  = (const float*)d_in[10];
    const float* rpb2_b  = (const float*)d_in[11];
    const float* proj_w  = (const float*)d_in[12];
    const float* proj_b  = (const float*)d_in[13];
    const float* norm2_w = (const float*)d_in[14];
    const float* norm2_b = (const float*)d_in[15];
    const float* fc1_w   = (const float*)d_in[16];
    const float* fc1_b   = (const float*)d_in[17];
    const float* fc2_w   = (const float*)d_in[18];
    const float* fc2_b   = (const float*)d_in[19];
    float* out = (float*)d_out;

    static int smem_set = 0;
    if (!smem_set) {
        cudaFuncSetAttribute(gemm_tc<0,256>,
            cudaFuncAttributeMaxDynamicSharedMemorySize, GSMEM_BYTES);
        cudaFuncSetAttribute(gemm_tc<1,256>,
            cudaFuncAttributeMaxDynamicSharedMemorySize, GSMEM_BYTES);
        cudaFuncSetAttribute(gemm_tc<2,256>,
            cudaFuncAttributeMaxDynamicSharedMemorySize, GSMEM_BYTES);
        cudaFuncSetAttribute(gemm_tc<3,1024>,
            cudaFuncAttributeMaxDynamicSharedMemorySize, GSMEM_BYTES);
        smem_set = 1;
    }

    convert_w_kernel<<<(W_TOT + 255)/256, 256>>>(qkv_w, proj_w, fc1_w, fc2_w);
    setup_bias_kernel<<<1, 256>>>(rpb1_w, rpb1_b, rpb2_w, rpb2_b);
    ape_ln_kernel<<<Bn*Hn, 256>>>(x, ape_w, ape_b, norm1_w, norm1_b);
    gemm_tc<0, 256><<<dim3(NPIX/128, 768/128),  256, GSMEM_BYTES>>>(W_QKV, qkv_b, nullptr);
    attn_kernel<<<dim3(NWIN, NHn), 128>>>(scale);
    gemm_tc<1, 256><<<dim3(NPIX/128, 256/128),  256, GSMEM_BYTES>>>(W_PROJ, proj_b, nullptr);
    ln2_kernel<<<NPIX/8, 256>>>(norm2_w, norm2_b);
    gemm_tc<2, 256><<<dim3(NPIX/128, 1024/128), 256, GSMEM_BYTES>>>(W_FC1, fc1_b, nullptr);
    gemm_tc<3, 1024><<<dim3(NPIX/128, 256/128), 256, GSMEM_BYTES>>>(W_FC2, fc2_b, out);
}

// round 16
// speedup vs baseline: 1.0245x; 1.0245x over previous
#include <cuda_runtime.h>
#include <cuda_bf16.h>
#include <math.h>
#include <stdint.h>

// ---------------- problem constants ----------------
#define Bn   16
#define Hn   56
#define Wn   56
#define Cn   256
#define NPIX (Bn*Hn*Wn)        // 50176 tokens
#define NHn  8
#define HDn  32
#define Ln   49
#define NWIN 1024
#define QS   (NWIN*NHn*Ln*HDn)
#define HIDn 1024

// weight buffer offsets (bf16 elems)
#define W_QKV  0
#define W_PROJ 196608
#define W_FC1  262144
#define W_FC2  524288
#define W_TOT  786432

// GEMM smem: 3 stages x 128 rows x 20 u32, A + B  (dynamic)
#define GSTG   (128*20)            // u32 per stage per matrix
#define NSTAGE 3
#define GSMEM_BYTES (NSTAGE*GSTG*2*4)   // 61440

// bias table: padded rows of 52 floats for aligned float2 reads
#define BROW 52

// ---------------- scratch ----------------
__device__ __nv_bfloat16 g_wh [W_TOT];
__device__ float         g_xa [NPIX*Cn];
__device__ __nv_bfloat16 g_ln1h[NPIX*Cn];
__device__ __nv_bfloat16 g_qkh[2*QS];              // q,k
__device__ uint32_t      g_vth[8192*1536];         // V^T bf16 slab layout, zero-init padding
__device__ __nv_bfloat16 g_atth[NPIX*Cn];
__device__ float         g_x2 [NPIX*Cn];
__device__ __nv_bfloat16 g_ln2h[NPIX*Cn];
__device__ __nv_bfloat16 g_mlph[NPIX*HIDn];
__device__ float g_bias[NHn*Ln*BROW + 16];         // padded, +16 guard for f2 tail

// ---------------- helpers ----------------
__device__ __forceinline__ int token_pixel(int t) {
    int win = t / Ln, l = t - win * Ln;
    int b  = win >> 6, wi = win & 63;
    int hr = (wi >> 3) * 7 + l / 7 + 3; if (hr >= 56) hr -= 56;
    int wr = (wi & 7)  * 7 + (l % 7) + 3; if (wr >= 56) wr -= 56;
    return (b * 56 + hr) * 56 + wr;
}

__device__ __forceinline__ uint32_t pack_bf16(float lo, float hi) {
    uint32_t u;
    asm("cvt.rn.bf16x2.f32 %0, %1, %2;" : "=r"(u) : "f"(hi), "f"(lo));
    return u;
}

__device__ __forceinline__ float gelu_exact(float v) {
    return 0.5f * v * (1.0f + erff(v * 0.7071067811865475f));
}

__device__ __forceinline__ void mma_bf16(float4& d, const uint32_t a[4], const uint32_t b[2]) {
    asm volatile(
        "mma.sync.aligned.m16n8k16.row.col.f32.bf16.bf16.f32 "
        "{%0,%1,%2,%3}, {%4,%5,%6,%7}, {%8,%9}, {%0,%1,%2,%3};\n"
        : "+f"(d.x), "+f"(d.y), "+f"(d.z), "+f"(d.w)
        : "r"(a[0]), "r"(a[1]), "r"(a[2]), "r"(a[3]), "r"(b[0]), "r"(b[1]));
}

__device__ __forceinline__ void ldmx4(uint32_t r[4], uint32_t addr) {
    asm volatile("ldmatrix.sync.aligned.m8n8.x4.shared.b16 {%0,%1,%2,%3}, [%4];"
        : "=r"(r[0]), "=r"(r[1]), "=r"(r[2]), "=r"(r[3]) : "r"(addr));
}

#define CP16(dst, src) \
    asm volatile("cp.async.cg.shared.global [%0], [%1], 16;" :: "r"(dst), "l"(src))
#define CP_COMMIT() asm volatile("cp.async.commit_group;")
#define CP_WAITG1() asm volatile("cp.async.wait_group 1;" ::: "memory")

__device__ __forceinline__ float warp_sum(float v) {
    #pragma unroll
    for (int o = 16; o > 0; o >>= 1) v += __shfl_xor_sync(0xffffffffu, v, o);
    return v;
}

// ---------------- weight conversion ----------------
__global__ void convert_w_kernel(const float* __restrict__ qkv,
                                 const float* __restrict__ proj,
                                 const float* __restrict__ fc1,
                                 const float* __restrict__ fc2) {
    int i = blockIdx.x * blockDim.x + threadIdx.x;
    if (i >= W_TOT) return;
    float v;
    if      (i < W_PROJ) v = qkv [i - W_QKV];
    else if (i < W_FC1)  v = proj[i - W_PROJ];
    else if (i < W_FC2)  v = fc1 [i - W_FC1];
    else                 v = fc2 [i - W_FC2];
    g_wh[i] = __float2bfloat16(v);
}

// ---------------- setup: bias table (padded rows of BROW) ----------------
__global__ void setup_bias_kernel(const float* __restrict__ rpb1_w,
                                  const float* __restrict__ rpb1_b,
                                  const float* __restrict__ rpb2_w,
                                  const float* __restrict__ rpb2_b) {
    __shared__ float table[169 * 8];
    int tid = threadIdx.x;
    if (tid < 169) {
        int a = tid / 13, b2 = tid % 13;
        float dy = (float)(a - 6), dx = (float)(b2 - 6);
        float r0 = (dy > 0.f ? 1.f : (dy < 0.f ? -1.f : 0.f)) * log1pf(fabsf(dy));
        float r1 = (dx > 0.f ? 1.f : (dx < 0.f ? -1.f : 0.f)) * log1pf(fabsf(dx));
        float acc[8] = {0,0,0,0,0,0,0,0};
        for (int j = 0; j < 512; j++) {
            float hj = fmaxf(0.f, r0 * rpb1_w[2*j] + r1 * rpb1_w[2*j+1] + rpb1_b[j]);
            #pragma unroll
            for (int h = 0; h < 8; h++) acc[h] += hj * rpb2_w[h*512 + j];
        }
        #pragma unroll
        for (int h = 0; h < 8; h++) table[tid*8 + h] = acc[h] + rpb2_b[h];
    }
    __syncthreads();
    for (int e = tid; e < NHn*Ln*Ln; e += blockDim.x) {
        int h = e / (Ln*Ln), r = e % (Ln*Ln), i = r / Ln, j = r % Ln;
        int idx = (i/7 - j/7 + 6) * 13 + (i%7 - j%7 + 6);
        g_bias[(h*Ln + i)*BROW + j] = table[idx*8 + h];
    }
}

__device__ __forceinline__ int shift_label(int t) { return t < 49 ? 0 : (t < 53 ? 1 : 2); }

// ---------------- K1: APE conv + residual + LN1 (smem-tiled) --------------
// One block per 8-pixel row segment; stage 3 rows x 10 px x 256 ch + weights
// in smem (one barrier), then warp-per-pixel with stride-32 channel mapping
// (lane owns banks = lane: conflict-free LDS) and shuffle-only LN.
__global__ void __launch_bounds__(256)
ape_ln_kernel(const float* __restrict__ x,  const float* __restrict__ apw,
              const float* __restrict__ apb, const float* __restrict__ nw,
              const float* __restrict__ nb) {
    __shared__ float sx[3][10][256];
    __shared__ float sw[9*256];
    __shared__ float sb[256], snw[256], snb[256];

    int tid = threadIdx.x;
    int blk = blockIdx.x;
    int seg = blk % 7;
    int h   = (blk / 7) % 56;
    int b   = blk / (7*56);
    int w0  = seg * 8;

    // stage weights
    #pragma unroll
    for (int i = 0; i < 9; i++) sw[i*256 + tid] = apw[i*256 + tid];
    sb[tid]  = apb[tid];
    snw[tid] = nw[tid];
    snb[tid] = nb[tid];

    // stage x tile: rows h-1..h+1, cols w0-1..w0+8 (zero at borders)
    #pragma unroll
    for (int it = 0; it < 8; it++) {                  // 1920 float4s / 256 thr
        int i = it*256 + tid;
        if (i < 1920) {
            int r  = i / 640;
            int cc = i - r*640;
            int p  = cc >> 6, c4 = cc & 63;
            int hh = h + r - 1, ww = w0 - 1 + p;
            float4 v = make_float4(0.f, 0.f, 0.f, 0.f);
            if ((unsigned)hh < 56u && (unsigned)ww < 56u)
                v = *(const float4*)(x + (((size_t)b*56 + hh)*56 + ww)*Cn + c4*4);
            *(float4*)&sx[r][p][c4*4] = v;
        }
    }
    __syncthreads();

    int wpb = tid >> 5, lane = tid & 31;     // warp wpb owns pixel w0+wpb
    float v[8];
    #pragma unroll
    for (int j = 0; j < 8; j++) {
        int c = lane + 32*j;
        float acc = sx[1][wpb+1][c] + sb[c];
        #pragma unroll
        for (int kh = 0; kh < 3; kh++)
            #pragma unroll
            for (int kw = 0; kw < 3; kw++)
                acc += sx[kh][wpb+kw][c] * sw[(kh*3+kw)*256 + c];
        v[j] = acc;
    }
    float s = 0.f, sq = 0.f;
    #pragma unroll
    for (int j = 0; j < 8; j++) { s += v[j]; sq += v[j]*v[j]; }
    s = warp_sum(s); sq = warp_sum(sq);
    float mean = s * (1.0f/256.0f);
    float var  = sq * (1.0f/256.0f) - mean*mean;
    float rstd = rsqrtf(var + 1e-5f);

    size_t base = (((size_t)b*56 + h)*56 + (w0 + wpb))*Cn;
    #pragma unroll
    for (int j = 0; j < 8; j++) {
        int c = lane + 32*j;
        g_xa[base + c]   = v[j];
        g_ln1h[base + c] = __float2bfloat16((v[j] - mean) * rstd * snw[c] + snb[c]);
    }
}

// ---------------- LN2 (warp per pixel) ----------------
__global__ void __launch_bounds__(256)
ln2_kernel(const float* __restrict__ nw, const float* __restrict__ nb) {
    int wpb = threadIdx.x >> 5, lane = threadIdx.x & 31;
    int p = blockIdx.x * 8 + wpb;
    int c0 = lane * 8;
    size_t idx = (size_t)p*Cn + c0;
    float4 s0 = *(const float4*)(g_x2 + idx), s1 = *(const float4*)(g_x2 + idx + 4);
    float v[8] = {s0.x,s0.y,s0.z,s0.w,s1.x,s1.y,s1.z,s1.w};
    float s = 0.f;
    #pragma unroll
    for (int i = 0; i < 8; i++) s += v[i];
    float mean = warp_sum(s) * (1.0f/256.0f);
    float d[8], sq = 0.f;
    #pragma unroll
    for (int i = 0; i < 8; i++) { d[i] = v[i] - mean; sq += d[i]*d[i]; }
    float rstd = rsqrtf(warp_sum(sq) * (1.0f/256.0f) + 1e-5f);
    float4 nwv0 = *(const float4*)(nw + c0), nwv1 = *(const float4*)(nw + c0 + 4);
    float4 nbv0 = *(const float4*)(nb + c0), nbv1 = *(const float4*)(nb + c0 + 4);
    float o[8];
    o[0]=d[0]*rstd*nwv0.x+nbv0.x; o[1]=d[1]*rstd*nwv0.y+nbv0.y;
    o[2]=d[2]*rstd*nwv0.z+nbv0.z; o[3]=d[3]*rstd*nwv0.w+nbv0.w;
    o[4]=d[4]*rstd*nwv1.x+nbv1.x; o[5]=d[5]*rstd*nwv1.y+nbv1.y;
    o[6]=d[6]*rstd*nwv1.z+nbv1.z; o[7]=d[7]*rstd*nwv1.w+nbv1.w;
    uint4 pk = make_uint4(pack_bf16(o[0],o[1]), pack_bf16(o[2],o[3]),
                          pack_bf16(o[4],o[5]), pack_bf16(o[6],o[7]));
    *(uint4*)(g_ln2h + idx) = pk;
}

// ---------------- bf16 TC GEMM, k-slab 32, 3-stage cp.async ---------------
template<int EPI, int KSIZE>
__global__ void __launch_bounds__(256, 2)
gemm_tc(int woff, const float* __restrict__ bvec, float* __restrict__ outp) {
    const __nv_bfloat16* A = (EPI == 0) ? g_ln1h : (EPI == 1) ? g_atth
                           : (EPI == 2) ? g_ln2h : g_mlph;
    const __nv_bfloat16* W = g_wh + woff;

    extern __shared__ __align__(16) uint32_t dsm[];
    uint32_t* Asm = dsm;                 // [3][128][20]
    uint32_t* Bsm = dsm + 3*GSTG;        // [3][128][20]
    __shared__ const __nv_bfloat16* rowp[128];

    int tid = threadIdx.x;
    int m0 = blockIdx.x * 128, n0 = blockIdx.y * 128;
    if (tid < 128) {
        int t = m0 + tid;
        rowp[tid] = (EPI == 0) ? (A + (size_t)token_pixel(t)*KSIZE)
                               : (A + (size_t)t*KSIZE);
    }
    __syncthreads();

    int lm = tid >> 1;
    int half = tid & 1;
    const __nv_bfloat16* Asrc = rowp[lm] + half*16;
    const __nv_bfloat16* Bsrc = W + (size_t)(n0 + lm) * KSIZE + half*16;

    uint32_t sA = (uint32_t)__cvta_generic_to_shared(Asm + lm*20 + half*8);
    uint32_t sB = (uint32_t)__cvta_generic_to_shared(Bsm + lm*20 + half*8);
    const int STG = GSTG*4;              // 10240 bytes per stage

    int wid = tid >> 5, lane = tid & 31;
    int wm = wid >> 2, wn = wid & 3;
    int g = lane >> 2, t4 = lane & 3;

    uint32_t a_row  = (uint32_t)(wm*64 + (lane & 15));
    uint32_t a_koff = (uint32_t)((lane >> 4) * 4);
    uint32_t b_row0 = (uint32_t)(wn*32 + ((lane >> 4) ? 8 : 0) + (lane & 7));
    uint32_t b_koff = (uint32_t)(((lane >> 3) & 1) * 4);
    uint32_t aBase = (uint32_t)__cvta_generic_to_shared(Asm + a_row*20 + a_koff);
    uint32_t bBase = (uint32_t)__cvta_generic_to_shared(Bsm + b_row0*20 + b_koff);

    float4 acc[4][4];
    #pragma unroll
    for (int i = 0; i < 4; i++)
        #pragma unroll
        for (int j = 0; j < 4; j++) acc[i][j] = make_float4(0.f,0.f,0.f,0.f);

    const int NSLAB = KSIZE / 32;
    CP16(sA, Asrc);        CP16(sA + 16, Asrc + 8);
    CP16(sB, Bsrc);        CP16(sB + 16, Bsrc + 8);         CP_COMMIT();
    CP16(sA + STG, Asrc + 32); CP16(sA + STG + 16, Asrc + 40);
    CP16(sB + STG, Bsrc + 32); CP16(sB + STG + 16, Bsrc + 40); CP_COMMIT();

    int buf = 0;
    for (int i = 0; i < NSLAB; i++) {
        CP_WAITG1();
        __syncthreads();
        int ip = i + 2;
        if (ip < NSLAB) {
            int pb = ip % 3;
            const __nv_bfloat16* as = Asrc + ip*32;
            const __nv_bfloat16* bs = Bsrc + ip*32;
            CP16(sA + pb*STG, as);      CP16(sA + pb*STG + 16, as + 8);
            CP16(sB + pb*STG, bs);      CP16(sB + pb*STG + 16, bs + 8);
        }
        CP_COMMIT();

        uint32_t ab = aBase + buf*STG;
        uint32_t bb = bBase + buf*STG;
        #pragma unroll
        for (int kh = 0; kh < 2; kh++) {
            uint32_t afr[4][4], bfr[2][4];
            #pragma unroll
            for (int mt = 0; mt < 4; mt++) ldmx4(afr[mt], ab + mt*1280 + kh*32);
            #pragma unroll
            for (int np = 0; np < 2; np++) ldmx4(bfr[np], bb + np*1280 + kh*32);
            #pragma unroll
            for (int mt = 0; mt < 4; mt++) {
                #pragma unroll
                for (int np = 0; np < 2; np++) {
                    mma_bf16(acc[mt][2*np  ], afr[mt], &bfr[np][0]);
                    mma_bf16(acc[mt][2*np+1], afr[mt], &bfr[np][2]);
                }
            }
        }
        buf = (buf == 2) ? 0 : buf + 1;
    }

    // ---------------- vectorized epilogues ----------------
    #pragma unroll
    for (int mt = 0; mt < 4; mt++) {
        int rbase = m0 + wm*64 + mt*16 + g;
        #pragma unroll
        for (int rr = 0; rr < 2; rr++) {
            int r = rbase + rr*8;
            int pix = 0, win = 0, l = 0;
            if (EPI == 0) { win = r / Ln; l = r - win*Ln; }
            if (EPI == 1) pix = token_pixel(r);
            #pragma unroll
            for (int nt = 0; nt < 4; nt++) {
                int c0 = n0 + wn*32 + nt*8 + 2*t4;   // even
                float v0 = (rr == 0 ? acc[mt][nt].x : acc[mt][nt].z);
                float v1 = (rr == 0 ? acc[mt][nt].y : acc[mt][nt].w);
                float val0 = v0 + bvec[c0];
                float val1 = v1 + bvec[c0 + 1];
                if (EPI == 0) {
                    int which = c0 >> 8, head = (c0 >> 5) & 7, hd = c0 & 31;
                    if (which < 2) {
                        size_t idx = (((size_t)(win<<3) + head)*Ln + l)*HDn + hd;
                        *(uint32_t*)&g_qkh[(size_t)which*QS + idx] = pack_bf16(val0, val1);
                    } else {
                        int slab = l >> 4;
                        __nv_bfloat16* vb = (__nv_bfloat16*)g_vth
                            + (size_t)((win<<3)+head)*3072 + (l & 15);
                        vb[(slab*32 + hd    )*24] = __float2bfloat16(val0);
                        vb[(slab*32 + hd + 1)*24] = __float2bfloat16(val1);
                    }
                } else if (EPI == 1) {
                    size_t idx = (size_t)pix*Cn + c0;
                    float2 xa = *(const float2*)&g_xa[idx];
                    *(float2*)&g_x2[idx] = make_float2(xa.x + val0, xa.y + val1);
                } else if (EPI == 2) {
                    *(uint32_t*)&g_mlph[(size_t)r*HIDn + c0] =
                        pack_bf16(gelu_exact(val0), gelu_exact(val1));
                } else {
                    size_t idx = (size_t)r*Cn + c0;
                    float2 x2 = *(const float2*)&g_x2[idx];
                    *(float2*)&outp[idx] = make_float2(x2.x + val0, x2.y + val1);
                }
            }
        }
    }
}

// ---------------- attention: raw-S MMA + deferred cosine norm -------------
__global__ void __launch_bounds__(128)
attn_kernel(const float* __restrict__ scale) {
    int win = blockIdx.x, head = blockIdx.y;
    int wh = win*NHn + head;
    __shared__ __align__(16) uint32_t qs[2][64][12];
    __shared__ __align__(16) uint32_t ks[2][64][12];
    __shared__ __align__(16) uint32_t ps[4][64][12];
    __shared__ __align__(16) uint32_t vt[4][32][12];
    __shared__ float qn[64], kn[64];

    int tid = threadIdx.x, lane = tid & 31, w = tid >> 5;

    // ---- copy q,k rows raw + compute inverse norms ----
    {
        const __nv_bfloat16* qg = g_qkh + (size_t)wh*Ln*HDn;
        bool isq = tid < 64;
        int r = isq ? tid : tid - 64;
        uint32_t (*dst)[12] = isq ? qs[0] : ks[0];
        float* nrm = isq ? qn : kn;
        if (r < Ln) {
            const __nv_bfloat16* src = (isq ? qg : qg + QS) + r*HDn;
            uint4 u0 = *(const uint4*)(src);
            uint4 u1 = *(const uint4*)(src + 8);
            uint4 u2 = *(const uint4*)(src + 16);
            uint4 u3 = *(const uint4*)(src + 24);
            *(uint4*)&dst[r][0] = u0;      *(uint4*)&dst[r][4] = u1;
            *(uint4*)&dst[64 + r][0] = u2; *(uint4*)&dst[64 + r][4] = u3;
            uint32_t uu[16] = {u0.x,u0.y,u0.z,u0.w, u1.x,u1.y,u1.z,u1.w,
                               u2.x,u2.y,u2.z,u2.w, u3.x,u3.y,u3.z,u3.w};
            float ssum = 0.f;
            #pragma unroll
            for (int i = 0; i < 16; i++) {
                __nv_bfloat162 b2 = *(__nv_bfloat162*)&uu[i];
                float fx = __bfloat162float(b2.x), fy = __bfloat162float(b2.y);
                ssum += fx*fx + fy*fy;
            }
            nrm[r] = 1.0f / fmaxf(sqrtf(ssum), 1e-12f);
        } else {
            uint4 z = make_uint4(0,0,0,0);
            *(uint4*)&dst[r][0] = z; *(uint4*)&dst[r][4] = z;
            *(uint4*)&dst[64 + r][0] = z; *(uint4*)&dst[64 + r][4] = z;
            nrm[r] = 0.f;
        }
    }
    // ---- copy V^T slabs ----
    {
        const uint4* vsrc = (const uint4*)(g_vth + (size_t)wh*1536);
        uint4* vdst = (uint4*)vt;
        #pragma unroll
        for (int i = 0; i < 3; i++) vdst[tid + i*128] = vsrc[tid + i*128];
    }
    __syncthreads();

    int g = lane >> 2, t4 = lane & 3;
    uint32_t aBase = (uint32_t)__cvta_generic_to_shared(&qs[0][w*16 + (lane&15)][(lane>>4)*4]);
    uint32_t bBase = (uint32_t)__cvta_generic_to_shared(
        &ks[0][((lane>>4) ? 8 : 0) + (lane&7)][((lane>>3)&1)*4]);

    // ---- S = q . k^T (raw, acc in registers) ----
    float4 acc[8];
    #pragma unroll
    for (int i = 0; i < 8; i++) acc[i] = make_float4(0.f,0.f,0.f,0.f);
    #pragma unroll
    for (int s = 0; s < 2; s++) {
        uint32_t afr[4], bfr[4][4];
        ldmx4(afr, aBase + s*64*48);
        #pragma unroll
        for (int np = 0; np < 4; np++) ldmx4(bfr[np], bBase + s*64*48 + np*16*48);
        #pragma unroll
        for (int np = 0; np < 4; np++) {
            mma_bf16(acc[2*np  ], afr, &bfr[np][0]);
            mma_bf16(acc[2*np+1], afr, &bfr[np][2]);
        }
    }

    // ---- in-register softmax with deferred normalization ----
    {
        float tsc = __expf(-scale[head]);
        int w63 = win & 63;
        int whh = w63 >> 3, www = w63 & 7;
        int i1 = w*16 + g, i2 = i1 + 8;
        bool v1r = i1 < Ln, v2r = i2 < Ln;
        int ci1 = v1r ? shift_label(whh*7 + i1/7)*3 + shift_label(www*7 + i1%7) : 0;
        int ci2 = v2r ? shift_label(whh*7 + i2/7)*3 + shift_label(www*7 + i2%7) : 0;
        float sc1 = v1r ? tsc * qn[i1] : 0.f;
        float sc2 = v2r ? tsc * qn[i2] : 0.f;
        const float2* b1v = (const float2*)(g_bias + ((size_t)head*Ln + (v1r ? i1 : 0))*BROW);
        const float2* b2v = (const float2*)(g_bias + ((size_t)head*Ln + (v2r ? i2 : 0))*BROW);
        const float2* knv = (const float2*)kn;

        float x1[16], x2[16];
        #pragma unroll
        for (int nt = 0; nt < 8; nt++) {
            int c = nt*8 + 2*t4;
            float2 bb1 = b1v[nt*4 + t4];
            float2 bb2 = b2v[nt*4 + t4];
            float2 kk  = knv[nt*4 + t4];
            #pragma unroll
            for (int jj = 0; jj < 2; jj++) {
                int j = c + jj;
                float va = (jj == 0 ? acc[nt].x : acc[nt].y);
                float vb = (jj == 0 ? acc[nt].z : acc[nt].w);
                float bj1 = (jj == 0 ? bb1.x : bb1.y);
                float bj2 = (jj == 0 ? bb2.x : bb2.y);
                float kj  = (jj == 0 ? kk.x  : kk.y);
                if (j < Ln) {
                    int cj = shift_label(whh*7 + j/7)*3 + shift_label(www*7 + j%7);
                    x1[nt*2+jj] = v1r ? va*sc1*kj + bj1 + ((cj != ci1) ? -100.f : 0.f) : -1e30f;
                    x2[nt*2+jj] = v2r ? vb*sc2*kj + bj2 + ((cj != ci2) ? -100.f : 0.f) : -1e30f;
                } else {
                    x1[nt*2+jj] = -1e30f;
                    x2[nt*2+jj] = -1e30f;
                }
            }
        }
        float m1 = -1e30f, m2 = -1e30f;
        #pragma unroll
        for (int k = 0; k < 16; k++) { m1 = fmaxf(m1, x1[k]); m2 = fmaxf(m2, x2[k]); }
        m1 = fmaxf(m1, __shfl_xor_sync(0xffffffffu, m1, 1));
        m1 = fmaxf(m1, __shfl_xor_sync(0xffffffffu, m1, 2));
        m2 = fmaxf(m2, __shfl_xor_sync(0xffffffffu, m2, 1));
        m2 = fmaxf(m2, __shfl_xor_sync(0xffffffffu, m2, 2));
        float s1 = 0.f, s2 = 0.f;
        #pragma unroll
        for (int k = 0; k < 16; k++) {
            x1[k] = __expf(x1[k] - m1); s1 += x1[k];
            x2[k] = __expf(x2[k] - m2); s2 += x2[k];
        }
        s1 += __shfl_xor_sync(0xffffffffu, s1, 1);
        s1 += __shfl_xor_sync(0xffffffffu, s1, 2);
        s2 += __shfl_xor_sync(0xffffffffu, s2, 1);
        s2 += __shfl_xor_sync(0xffffffffu, s2, 2);
        float inv1 = 1.0f / s1, inv2 = 1.0f / s2;

        uint32_t* pf = (uint32_t*)ps;
        #pragma unroll
        for (int nt = 0; nt < 8; nt++) {
            int c = nt*8 + 2*t4;
            int sb = (c >> 4), cc = (c & 15) >> 1;
            pf[(sb*64 + i1)*12 + cc] = pack_bf16(x1[2*nt]*inv1, x1[2*nt+1]*inv1);
            pf[(sb*64 + i2)*12 + cc] = pack_bf16(x2[2*nt]*inv2, x2[2*nt+1]*inv2);
        }
    }
    __syncthreads();

    // ---- out = P . V ----
    {
        uint32_t pBase = (uint32_t)__cvta_generic_to_shared(
            &ps[0][w*16 + (lane&15)][(lane>>4)*4]);
        uint32_t vBase = (uint32_t)__cvta_generic_to_shared(
            &vt[0][((lane>>4) ? 8 : 0) + (lane&7)][((lane>>3)&1)*4]);
        float4 o[4];
        #pragma unroll
        for (int i = 0; i < 4; i++) o[i] = make_float4(0.f,0.f,0.f,0.f);
        #pragma unroll
        for (int s = 0; s < 4; s++) {
            uint32_t afr[4], bfr[2][4];
            ldmx4(afr, pBase + s*64*48);
            #pragma unroll
            for (int np = 0; np < 2; np++) ldmx4(bfr[np], vBase + s*32*48 + np*16*48);
            mma_bf16(o[0], afr, &bfr[0][0]);
            mma_bf16(o[1], afr, &bfr[0][2]);
            mma_bf16(o[2], afr, &bfr[1][0]);
            mma_bf16(o[3], afr, &bfr[1][2]);
        }
        __nv_bfloat16* ob = g_atth + ((size_t)win*Ln)*Cn + head*HDn;
        int i0 = w*16 + g;
        #pragma unroll
        for (int nt = 0; nt < 4; nt++) {
            int c = nt*8 + 2*t4;   // even
            if (i0 < Ln)
                *(uint32_t*)&ob[i0*Cn + c] = pack_bf16(o[nt].x, o[nt].y);
            if (i0 + 8 < Ln)
                *(uint32_t*)&ob[(i0+8)*Cn + c] = pack_bf16(o[nt].z, o[nt].w);
        }
    }
}

// ---------------- launch ----------------
extern "C" void kernel_launch(void* const* d_in, const int* in_sizes, int n_in,
                              void* d_out, int out_size) {
    const float* x       = (const float*)d_in[0];
    const float* ape_w   = (const float*)d_in[1];
    const float* ape_b   = (const float*)d_in[2];
    const float* norm1_w = (const float*)d_in[3];
    const float* norm1_b = (const float*)d_in[4];
    const float* qkv_w   = (const float*)d_in[5];
    const float* qkv_b   = (const float*)d_in[6];
    const float* scale   = (const float*)d_in[7];
    const float* rpb1_w  = (const float*)d_in[8];
    const float* rpb1_b  = (const float*)d_in[9];
    const float* rpb2_w  = (const float*)d_in[10];
    const float* rpb2_b  = (const float*)d_in[11];
    const float* proj_w  = (const float*)d_in[12];
    const float* proj_b  = (const float*)d_in[13];
    const float* norm2_w = (const float*)d_in[14];
    const float* norm2_b = (const float*)d_in[15];
    const float* fc1_w   = (const float*)d_in[16];
    const float* fc1_b   = (const float*)d_in[17];
    const float* fc2_w   = (const float*)d_in[18];
    const float* fc2_b   = (const float*)d_in[19];
    float* out = (float*)d_out;

    static int smem_set = 0;
    if (!smem_set) {
        cudaFuncSetAttribute(gemm_tc<0,256>,
            cudaFuncAttributeMaxDynamicSharedMemorySize, GSMEM_BYTES);
        cudaFuncSetAttribute(gemm_tc<1,256>,
            cudaFuncAttributeMaxDynamicSharedMemorySize, GSMEM_BYTES);
        cudaFuncSetAttribute(gemm_tc<2,256>,
            cudaFuncAttributeMaxDynamicSharedMemorySize, GSMEM_BYTES);
        cudaFuncSetAttribute(gemm_tc<3,1024>,
            cudaFuncAttributeMaxDynamicSharedMemorySize, GSMEM_BYTES);
        smem_set = 1;
    }

    convert_w_kernel<<<(W_TOT + 255)/256, 256>>>(qkv_w, proj_w, fc1_w, fc2_w);
    setup_bias_kernel<<<1, 256>>>(rpb1_w, rpb1_b, rpb2_w, rpb2_b);
    ape_ln_kernel<<<Bn*Hn*7, 256>>>(x, ape_w, ape_b, norm1_w, norm1_b);
    gemm_tc<0, 256><<<dim3(NPIX/128, 768/128),  256, GSMEM_BYTES>>>(W_QKV, qkv_b, nullptr);
    attn_kernel<<<dim3(NWIN, NHn), 128>>>(scale);
    gemm_tc<1, 256><<<dim3(NPIX/128, 256/128),  256, GSMEM_BYTES>>>(W_PROJ, proj_b, nullptr);
    ln2_kernel<<<NPIX/8, 256>>>(norm2_w, norm2_b);
    gemm_tc<2, 256><<<dim3(NPIX/128, 1024/128), 256, GSMEM_BYTES>>>(W_FC1, fc1_b, nullptr);
    gemm_tc<3, 1024><<<dim3(NPIX/128, 256/128), 256, GSMEM_BYTES>>>(W_FC2, fc2_b, out);
}

// round 17
// speedup vs baseline: 1.1372x; 1.1100x over previous
#include <cuda_runtime.h>
#include <cuda_bf16.h>
#include <math.h>
#include <stdint.h>

// ---------------- problem constants ----------------
#define Bn   16
#define Hn   56
#define Wn   56
#define Cn   256
#define NPIX (Bn*Hn*Wn)        // 50176 tokens
#define NHn  8
#define HDn  32
#define Ln   49
#define NWIN 1024
#define QS   (NWIN*NHn*Ln*HDn)
#define HIDn 1024

// weight buffer offsets (bf16 elems)
#define W_QKV  0
#define W_PROJ 196608
#define W_FC1  262144
#define W_FC2  524288
#define W_TOT  786432

// GEMM smem: 3 stages x 128 rows x 20 u32, A + B  (dynamic)
#define GSTG   (128*20)            // u32 per stage per matrix
#define NSTAGE 3
#define GSMEM_BYTES (NSTAGE*GSTG*2*4)   // 61440

// bias table: padded rows of 52 floats for aligned float2 reads
#define BROW 52

// ---------------- scratch ----------------
__device__ __nv_bfloat16 g_wh [W_TOT];
__device__ float         g_xa [NPIX*Cn];
__device__ __nv_bfloat16 g_ln1h[NPIX*Cn];
__device__ __nv_bfloat16 g_qkh[2*QS];              // q,k
__device__ uint32_t      g_vth[8192*1536];         // V^T bf16 slab layout, zero-init padding
__device__ __nv_bfloat16 g_atth[NPIX*Cn];
__device__ float         g_x2 [NPIX*Cn];
__device__ __nv_bfloat16 g_ln2h[NPIX*Cn];
__device__ __nv_bfloat16 g_mlph[NPIX*HIDn];
__device__ float g_table[169*8];                   // rel-pos MLP table
__device__ float g_bias[NHn*Ln*BROW + 16];         // padded, +16 guard for f2 tail

// ---------------- helpers ----------------
__device__ __forceinline__ int token_pixel(int t) {
    int win = t / Ln, l = t - win * Ln;
    int b  = win >> 6, wi = win & 63;
    int hr = (wi >> 3) * 7 + l / 7 + 3; if (hr >= 56) hr -= 56;
    int wr = (wi & 7)  * 7 + (l % 7) + 3; if (wr >= 56) wr -= 56;
    return (b * 56 + hr) * 56 + wr;
}

__device__ __forceinline__ uint32_t pack_bf16(float lo, float hi) {
    uint32_t u;
    asm("cvt.rn.bf16x2.f32 %0, %1, %2;" : "=r"(u) : "f"(hi), "f"(lo));
    return u;
}

__device__ __forceinline__ float gelu_exact(float v) {
    return 0.5f * v * (1.0f + erff(v * 0.7071067811865475f));
}

__device__ __forceinline__ void mma_bf16(float4& d, const uint32_t a[4], const uint32_t b[2]) {
    asm volatile(
        "mma.sync.aligned.m16n8k16.row.col.f32.bf16.bf16.f32 "
        "{%0,%1,%2,%3}, {%4,%5,%6,%7}, {%8,%9}, {%0,%1,%2,%3};\n"
        : "+f"(d.x), "+f"(d.y), "+f"(d.z), "+f"(d.w)
        : "r"(a[0]), "r"(a[1]), "r"(a[2]), "r"(a[3]), "r"(b[0]), "r"(b[1]));
}

__device__ __forceinline__ void ldmx4(uint32_t r[4], uint32_t addr) {
    asm volatile("ldmatrix.sync.aligned.m8n8.x4.shared.b16 {%0,%1,%2,%3}, [%4];"
        : "=r"(r[0]), "=r"(r[1]), "=r"(r[2]), "=r"(r[3]) : "r"(addr));
}

#define CP16(dst, src) \
    asm volatile("cp.async.cg.shared.global [%0], [%1], 16;" :: "r"(dst), "l"(src))
#define CP_COMMIT() asm volatile("cp.async.commit_group;")
#define CP_WAITG1() asm volatile("cp.async.wait_group 1;" ::: "memory")

__device__ __forceinline__ float warp_sum(float v) {
    #pragma unroll
    for (int o = 16; o > 0; o >>= 1) v += __shfl_xor_sync(0xffffffffu, v, o);
    return v;
}

// ---------------- weight conversion ----------------
__global__ void convert_w_kernel(const float* __restrict__ qkv,
                                 const float* __restrict__ proj,
                                 const float* __restrict__ fc1,
                                 const float* __restrict__ fc2) {
    int i = blockIdx.x * blockDim.x + threadIdx.x;
    if (i >= W_TOT) return;
    float v;
    if      (i < W_PROJ) v = qkv [i - W_QKV];
    else if (i < W_FC1)  v = proj[i - W_PROJ];
    else if (i < W_FC2)  v = fc1 [i - W_FC1];
    else                 v = fc2 [i - W_FC2];
    g_wh[i] = __float2bfloat16(v);
}

// ---------------- setup: rel-pos table (169 blocks, warp per (pos,head)) --
__global__ void setup_table_kernel(const float* __restrict__ rpb1_w,
                                   const float* __restrict__ rpb1_b,
                                   const float* __restrict__ rpb2_w,
                                   const float* __restrict__ rpb2_b) {
    int pos = blockIdx.x;
    int h = threadIdx.x >> 5, lane = threadIdx.x & 31;
    int a = pos / 13, b2 = pos % 13;
    float dy = (float)(a - 6), dx = (float)(b2 - 6);
    float r0 = (dy > 0.f ? 1.f : (dy < 0.f ? -1.f : 0.f)) * log1pf(fabsf(dy));
    float r1 = (dx > 0.f ? 1.f : (dx < 0.f ? -1.f : 0.f)) * log1pf(fabsf(dx));
    float acc = 0.f;
    for (int j = lane; j < 512; j += 32) {
        float hj = fmaxf(0.f, r0 * rpb1_w[2*j] + r1 * rpb1_w[2*j+1] + rpb1_b[j]);
        acc += hj * rpb2_w[h*512 + j];
    }
    acc = warp_sum(acc);
    if (lane == 0) g_table[pos*8 + h] = acc + rpb2_b[h];
}

// scatter table -> padded bias rows
__global__ void setup_bias_kernel2() {
    int e = blockIdx.x * blockDim.x + threadIdx.x;
    if (e >= NHn*Ln*Ln) return;
    int h = e / (Ln*Ln), r = e % (Ln*Ln), i = r / Ln, j = r % Ln;
    int idx = (i/7 - j/7 + 6) * 13 + (i%7 - j%7 + 6);
    g_bias[(h*Ln + i)*BROW + j] = g_table[idx*8 + h];
}

__device__ __forceinline__ int shift_label(int t) { return t < 49 ? 0 : (t < 53 ? 1 : 2); }

// ---------------- K1: APE conv + residual + LN1 (smem-tiled) --------------
__global__ void __launch_bounds__(256)
ape_ln_kernel(const float* __restrict__ x,  const float* __restrict__ apw,
              const float* __restrict__ apb, const float* __restrict__ nw,
              const float* __restrict__ nb) {
    __shared__ float sx[3][10][256];
    __shared__ float sw[9*256];
    __shared__ float sb[256], snw[256], snb[256];

    int tid = threadIdx.x;
    int blk = blockIdx.x;
    int seg = blk % 7;
    int h   = (blk / 7) % 56;
    int b   = blk / (7*56);
    int w0  = seg * 8;

    #pragma unroll
    for (int i = 0; i < 9; i++) sw[i*256 + tid] = apw[i*256 + tid];
    sb[tid]  = apb[tid];
    snw[tid] = nw[tid];
    snb[tid] = nb[tid];

    #pragma unroll
    for (int it = 0; it < 8; it++) {
        int i = it*256 + tid;
        if (i < 1920) {
            int r  = i / 640;
            int cc = i - r*640;
            int p  = cc >> 6, c4 = cc & 63;
            int hh = h + r - 1, ww = w0 - 1 + p;
            float4 v = make_float4(0.f, 0.f, 0.f, 0.f);
            if ((unsigned)hh < 56u && (unsigned)ww < 56u)
                v = *(const float4*)(x + (((size_t)b*56 + hh)*56 + ww)*Cn + c4*4);
            *(float4*)&sx[r][p][c4*4] = v;
        }
    }
    __syncthreads();

    int wpb = tid >> 5, lane = tid & 31;
    float v[8];
    #pragma unroll
    for (int j = 0; j < 8; j++) {
        int c = lane + 32*j;
        float acc = sx[1][wpb+1][c] + sb[c];
        #pragma unroll
        for (int kh = 0; kh < 3; kh++)
            #pragma unroll
            for (int kw = 0; kw < 3; kw++)
                acc += sx[kh][wpb+kw][c] * sw[(kh*3+kw)*256 + c];
        v[j] = acc;
    }
    float s = 0.f, sq = 0.f;
    #pragma unroll
    for (int j = 0; j < 8; j++) { s += v[j]; sq += v[j]*v[j]; }
    s = warp_sum(s); sq = warp_sum(sq);
    float mean = s * (1.0f/256.0f);
    float var  = sq * (1.0f/256.0f) - mean*mean;
    float rstd = rsqrtf(var + 1e-5f);

    size_t base = (((size_t)b*56 + h)*56 + (w0 + wpb))*Cn;
    #pragma unroll
    for (int j = 0; j < 8; j++) {
        int c = lane + 32*j;
        g_xa[base + c]   = v[j];
        g_ln1h[base + c] = __float2bfloat16((v[j] - mean) * rstd * snw[c] + snb[c]);
    }
}

// ---------------- LN2 (warp per pixel) ----------------
__global__ void __launch_bounds__(256)
ln2_kernel(const float* __restrict__ nw, const float* __restrict__ nb) {
    int wpb = threadIdx.x >> 5, lane = threadIdx.x & 31;
    int p = blockIdx.x * 8 + wpb;
    int c0 = lane * 8;
    size_t idx = (size_t)p*Cn + c0;
    float4 s0 = *(const float4*)(g_x2 + idx), s1 = *(const float4*)(g_x2 + idx + 4);
    float v[8] = {s0.x,s0.y,s0.z,s0.w,s1.x,s1.y,s1.z,s1.w};
    float s = 0.f;
    #pragma unroll
    for (int i = 0; i < 8; i++) s += v[i];
    float mean = warp_sum(s) * (1.0f/256.0f);
    float d[8], sq = 0.f;
    #pragma unroll
    for (int i = 0; i < 8; i++) { d[i] = v[i] - mean; sq += d[i]*d[i]; }
    float rstd = rsqrtf(warp_sum(sq) * (1.0f/256.0f) + 1e-5f);
    float4 nwv0 = *(const float4*)(nw + c0), nwv1 = *(const float4*)(nw + c0 + 4);
    float4 nbv0 = *(const float4*)(nb + c0), nbv1 = *(const float4*)(nb + c0 + 4);
    float o[8];
    o[0]=d[0]*rstd*nwv0.x+nbv0.x; o[1]=d[1]*rstd*nwv0.y+nbv0.y;
    o[2]=d[2]*rstd*nwv0.z+nbv0.z; o[3]=d[3]*rstd*nwv0.w+nbv0.w;
    o[4]=d[4]*rstd*nwv1.x+nbv1.x; o[5]=d[5]*rstd*nwv1.y+nbv1.y;
    o[6]=d[6]*rstd*nwv1.z+nbv1.z; o[7]=d[7]*rstd*nwv1.w+nbv1.w;
    uint4 pk = make_uint4(pack_bf16(o[0],o[1]), pack_bf16(o[2],o[3]),
                          pack_bf16(o[4],o[5]), pack_bf16(o[6],o[7]));
    *(uint4*)(g_ln2h + idx) = pk;
}

// ---------------- bf16 TC GEMM, k-slab 32, 3-stage cp.async ---------------
template<int EPI, int KSIZE>
__global__ void __launch_bounds__(256, 2)
gemm_tc(int woff, const float* __restrict__ bvec, float* __restrict__ outp) {
    const __nv_bfloat16* A = (EPI == 0) ? g_ln1h : (EPI == 1) ? g_atth
                           : (EPI == 2) ? g_ln2h : g_mlph;
    const __nv_bfloat16* W = g_wh + woff;

    extern __shared__ __align__(16) uint32_t dsm[];
    uint32_t* Asm = dsm;                 // [3][128][20]
    uint32_t* Bsm = dsm + 3*GSTG;        // [3][128][20]
    __shared__ const __nv_bfloat16* rowp[128];

    int tid = threadIdx.x;
    int m0 = blockIdx.x * 128, n0 = blockIdx.y * 128;
    if (tid < 128) {
        int t = m0 + tid;
        rowp[tid] = (EPI == 0) ? (A + (size_t)token_pixel(t)*KSIZE)
                               : (A + (size_t)t*KSIZE);
    }
    __syncthreads();

    int lm = tid >> 1;
    int half = tid & 1;
    const __nv_bfloat16* Asrc = rowp[lm] + half*16;
    const __nv_bfloat16* Bsrc = W + (size_t)(n0 + lm) * KSIZE + half*16;

    uint32_t sA = (uint32_t)__cvta_generic_to_shared(Asm + lm*20 + half*8);
    uint32_t sB = (uint32_t)__cvta_generic_to_shared(Bsm + lm*20 + half*8);
    const int STG = GSTG*4;              // 10240 bytes per stage

    int wid = tid >> 5, lane = tid & 31;
    int wm = wid >> 2, wn = wid & 3;
    int g = lane >> 2, t4 = lane & 3;

    uint32_t a_row  = (uint32_t)(wm*64 + (lane & 15));
    uint32_t a_koff = (uint32_t)((lane >> 4) * 4);
    uint32_t b_row0 = (uint32_t)(wn*32 + ((lane >> 4) ? 8 : 0) + (lane & 7));
    uint32_t b_koff = (uint32_t)(((lane >> 3) & 1) * 4);
    uint32_t aBase = (uint32_t)__cvta_generic_to_shared(Asm + a_row*20 + a_koff);
    uint32_t bBase = (uint32_t)__cvta_generic_to_shared(Bsm + b_row0*20 + b_koff);

    float4 acc[4][4];
    #pragma unroll
    for (int i = 0; i < 4; i++)
        #pragma unroll
        for (int j = 0; j < 4; j++) acc[i][j] = make_float4(0.f,0.f,0.f,0.f);

    const int NSLAB = KSIZE / 32;
    CP16(sA, Asrc);        CP16(sA + 16, Asrc + 8);
    CP16(sB, Bsrc);        CP16(sB + 16, Bsrc + 8);         CP_COMMIT();
    CP16(sA + STG, Asrc + 32); CP16(sA + STG + 16, Asrc + 40);
    CP16(sB + STG, Bsrc + 32); CP16(sB + STG + 16, Bsrc + 40); CP_COMMIT();

    int buf = 0;
    for (int i = 0; i < NSLAB; i++) {
        CP_WAITG1();
        __syncthreads();
        int ip = i + 2;
        if (ip < NSLAB) {
            int pb = ip % 3;
            const __nv_bfloat16* as = Asrc + ip*32;
            const __nv_bfloat16* bs = Bsrc + ip*32;
            CP16(sA + pb*STG, as);      CP16(sA + pb*STG + 16, as + 8);
            CP16(sB + pb*STG, bs);      CP16(sB + pb*STG + 16, bs + 8);
        }
        CP_COMMIT();

        uint32_t ab = aBase + buf*STG;
        uint32_t bb = bBase + buf*STG;
        #pragma unroll
        for (int kh = 0; kh < 2; kh++) {
            uint32_t afr[4][4], bfr[2][4];
            #pragma unroll
            for (int mt = 0; mt < 4; mt++) ldmx4(afr[mt], ab + mt*1280 + kh*32);
            #pragma unroll
            for (int np = 0; np < 2; np++) ldmx4(bfr[np], bb + np*1280 + kh*32);
            #pragma unroll
            for (int mt = 0; mt < 4; mt++) {
                #pragma unroll
                for (int np = 0; np < 2; np++) {
                    mma_bf16(acc[mt][2*np  ], afr[mt], &bfr[np][0]);
                    mma_bf16(acc[mt][2*np+1], afr[mt], &bfr[np][2]);
                }
            }
        }
        buf = (buf == 2) ? 0 : buf + 1;
    }

    // ---------------- vectorized epilogues ----------------
    #pragma unroll
    for (int mt = 0; mt < 4; mt++) {
        int rbase = m0 + wm*64 + mt*16 + g;
        #pragma unroll
        for (int rr = 0; rr < 2; rr++) {
            int r = rbase + rr*8;
            int pix = 0, win = 0, l = 0;
            if (EPI == 0) { win = r / Ln; l = r - win*Ln; }
            if (EPI == 1) pix = token_pixel(r);
            #pragma unroll
            for (int nt = 0; nt < 4; nt++) {
                int c0 = n0 + wn*32 + nt*8 + 2*t4;   // even
                float v0 = (rr == 0 ? acc[mt][nt].x : acc[mt][nt].z);
                float v1 = (rr == 0 ? acc[mt][nt].y : acc[mt][nt].w);
                float val0 = v0 + bvec[c0];
                float val1 = v1 + bvec[c0 + 1];
                if (EPI == 0) {
                    int which = c0 >> 8, head = (c0 >> 5) & 7, hd = c0 & 31;
                    if (which < 2) {
                        size_t idx = (((size_t)(win<<3) + head)*Ln + l)*HDn + hd;
                        *(uint32_t*)&g_qkh[(size_t)which*QS + idx] = pack_bf16(val0, val1);
                    } else {
                        int slab = l >> 4;
                        __nv_bfloat16* vb = (__nv_bfloat16*)g_vth
                            + (size_t)((win<<3)+head)*3072 + (l & 15);
                        vb[(slab*32 + hd    )*24] = __float2bfloat16(val0);
                        vb[(slab*32 + hd + 1)*24] = __float2bfloat16(val1);
                    }
                } else if (EPI == 1) {
                    size_t idx = (size_t)pix*Cn + c0;
                    float2 xa = *(const float2*)&g_xa[idx];
                    *(float2*)&g_x2[idx] = make_float2(xa.x + val0, xa.y + val1);
                } else if (EPI == 2) {
                    *(uint32_t*)&g_mlph[(size_t)r*HIDn + c0] =
                        pack_bf16(gelu_exact(val0), gelu_exact(val1));
                } else {
                    size_t idx = (size_t)r*Cn + c0;
                    float2 x2 = *(const float2*)&g_x2[idx];
                    *(float2*)&outp[idx] = make_float2(x2.x + val0, x2.y + val1);
                }
            }
        }
    }
}

// ---------------- attention: raw-S MMA + deferred cosine norm -------------
// smem: P slabs alias the q/k region (dead after the S MMA); one extra
// barrier guards the overwrite.  19 KB/block -> ~12 blocks/SM.
__global__ void __launch_bounds__(128)
attn_kernel(const float* __restrict__ scale) {
    int win = blockIdx.x, head = blockIdx.y;
    int wh = win*NHn + head;
    __shared__ __align__(16) uint32_t sh[3072];    // qs[2][64][12] + ks[2][64][12]; reused as ps[4][64][12]
    __shared__ __align__(16) uint32_t vt[4][32][12];
    __shared__ float qn[64], kn[64];

    uint32_t (*qs)[12] = (uint32_t(*)[12])sh;            // rows 0..127 (2 slabs)
    uint32_t (*ks)[12] = (uint32_t(*)[12])(sh + 1536);   // rows 0..127 (2 slabs)

    int tid = threadIdx.x, lane = tid & 31, w = tid >> 5;

    // ---- copy q,k rows raw + compute inverse norms ----
    {
        const __nv_bfloat16* qg = g_qkh + (size_t)wh*Ln*HDn;
        bool isq = tid < 64;
        int r = isq ? tid : tid - 64;
        uint32_t (*dst)[12] = isq ? qs : ks;
        float* nrm = isq ? qn : kn;
        if (r < Ln) {
            const __nv_bfloat16* src = (isq ? qg : qg + QS) + r*HDn;
            uint4 u0 = *(const uint4*)(src);
            uint4 u1 = *(const uint4*)(src + 8);
            uint4 u2 = *(const uint4*)(src + 16);
            uint4 u3 = *(const uint4*)(src + 24);
            *(uint4*)&dst[r][0] = u0;      *(uint4*)&dst[r][4] = u1;
            *(uint4*)&dst[64 + r][0] = u2; *(uint4*)&dst[64 + r][4] = u3;
            uint32_t uu[16] = {u0.x,u0.y,u0.z,u0.w, u1.x,u1.y,u1.z,u1.w,
                               u2.x,u2.y,u2.z,u2.w, u3.x,u3.y,u3.z,u3.w};
            float ssum = 0.f;
            #pragma unroll
            for (int i = 0; i < 16; i++) {
                __nv_bfloat162 b2 = *(__nv_bfloat162*)&uu[i];
                float fx = __bfloat162float(b2.x), fy = __bfloat162float(b2.y);
                ssum += fx*fx + fy*fy;
            }
            nrm[r] = 1.0f / fmaxf(sqrtf(ssum), 1e-12f);
        } else {
            uint4 z = make_uint4(0,0,0,0);
            *(uint4*)&dst[r][0] = z; *(uint4*)&dst[r][4] = z;
            *(uint4*)&dst[64 + r][0] = z; *(uint4*)&dst[64 + r][4] = z;
            nrm[r] = 0.f;
        }
    }
    // ---- copy V^T slabs ----
    {
        const uint4* vsrc = (const uint4*)(g_vth + (size_t)wh*1536);
        uint4* vdst = (uint4*)vt;
        #pragma unroll
        for (int i = 0; i < 3; i++) vdst[tid + i*128] = vsrc[tid + i*128];
    }
    __syncthreads();

    int g = lane >> 2, t4 = lane & 3;
    uint32_t aBase = (uint32_t)__cvta_generic_to_shared(&qs[w*16 + (lane&15)][(lane>>4)*4]);
    uint32_t bBase = (uint32_t)__cvta_generic_to_shared(
        &ks[((lane>>4) ? 8 : 0) + (lane&7)][((lane>>3)&1)*4]);

    // ---- S = q . k^T (raw, acc in registers) ----
    float4 acc[8];
    #pragma unroll
    for (int i = 0; i < 8; i++) acc[i] = make_float4(0.f,0.f,0.f,0.f);
    #pragma unroll
    for (int s = 0; s < 2; s++) {
        uint32_t afr[4], bfr[4][4];
        ldmx4(afr, aBase + s*64*48);
        #pragma unroll
        for (int np = 0; np < 4; np++) ldmx4(bfr[np], bBase + s*64*48 + np*16*48);
        #pragma unroll
        for (int np = 0; np < 4; np++) {
            mma_bf16(acc[2*np  ], afr, &bfr[np][0]);
            mma_bf16(acc[2*np+1], afr, &bfr[np][2]);
        }
    }
    __syncthreads();    // all warps done reading qs/ks before P overwrites them

    // ---- in-register softmax with deferred normalization ----
    {
        float tsc = __expf(-scale[head]);
        int w63 = win & 63;
        int whh = w63 >> 3, www = w63 & 7;
        int i1 = w*16 + g, i2 = i1 + 8;
        bool v1r = i1 < Ln, v2r = i2 < Ln;
        int ci1 = v1r ? shift_label(whh*7 + i1/7)*3 + shift_label(www*7 + i1%7) : 0;
        int ci2 = v2r ? shift_label(whh*7 + i2/7)*3 + shift_label(www*7 + i2%7) : 0;
        float sc1 = v1r ? tsc * qn[i1] : 0.f;
        float sc2 = v2r ? tsc * qn[i2] : 0.f;
        const float2* b1v = (const float2*)(g_bias + ((size_t)head*Ln + (v1r ? i1 : 0))*BROW);
        const float2* b2v = (const float2*)(g_bias + ((size_t)head*Ln + (v2r ? i2 : 0))*BROW);
        const float2* knv = (const float2*)kn;

        float x1[16], x2[16];
        #pragma unroll
        for (int nt = 0; nt < 8; nt++) {
            int c = nt*8 + 2*t4;
            float2 bb1 = b1v[nt*4 + t4];
            float2 bb2 = b2v[nt*4 + t4];
            float2 kk  = knv[nt*4 + t4];
            #pragma unroll
            for (int jj = 0; jj < 2; jj++) {
                int j = c + jj;
                float va = (jj == 0 ? acc[nt].x : acc[nt].y);
                float vb = (jj == 0 ? acc[nt].z : acc[nt].w);
                float bj1 = (jj == 0 ? bb1.x : bb1.y);
                float bj2 = (jj == 0 ? bb2.x : bb2.y);
                float kj  = (jj == 0 ? kk.x  : kk.y);
                if (j < Ln) {
                    int cj = shift_label(whh*7 + j/7)*3 + shift_label(www*7 + j%7);
                    x1[nt*2+jj] = v1r ? va*sc1*kj + bj1 + ((cj != ci1) ? -100.f : 0.f) : -1e30f;
                    x2[nt*2+jj] = v2r ? vb*sc2*kj + bj2 + ((cj != ci2) ? -100.f : 0.f) : -1e30f;
                } else {
                    x1[nt*2+jj] = -1e30f;
                    x2[nt*2+jj] = -1e30f;
                }
            }
        }
        float m1 = -1e30f, m2 = -1e30f;
        #pragma unroll
        for (int k = 0; k < 16; k++) { m1 = fmaxf(m1, x1[k]); m2 = fmaxf(m2, x2[k]); }
        m1 = fmaxf(m1, __shfl_xor_sync(0xffffffffu, m1, 1));
        m1 = fmaxf(m1, __shfl_xor_sync(0xffffffffu, m1, 2));
        m2 = fmaxf(m2, __shfl_xor_sync(0xffffffffu, m2, 1));
        m2 = fmaxf(m2, __shfl_xor_sync(0xffffffffu, m2, 2));
        float s1 = 0.f, s2 = 0.f;
        #pragma unroll
        for (int k = 0; k < 16; k++) {
            x1[k] = __expf(x1[k] - m1); s1 += x1[k];
            x2[k] = __expf(x2[k] - m2); s2 += x2[k];
        }
        s1 += __shfl_xor_sync(0xffffffffu, s1, 1);
        s1 += __shfl_xor_sync(0xffffffffu, s1, 2);
        s2 += __shfl_xor_sync(0xffffffffu, s2, 1);
        s2 += __shfl_xor_sync(0xffffffffu, s2, 2);
        float inv1 = 1.0f / s1, inv2 = 1.0f / s2;

        uint32_t* pf = sh;    // P slabs overwrite q/k region
        #pragma unroll
        for (int nt = 0; nt < 8; nt++) {
            int c = nt*8 + 2*t4;
            int sb = (c >> 4), cc = (c & 15) >> 1;
            pf[(sb*64 + i1)*12 + cc] = pack_bf16(x1[2*nt]*inv1, x1[2*nt+1]*inv1);
            pf[(sb*64 + i2)*12 + cc] = pack_bf16(x2[2*nt]*inv2, x2[2*nt+1]*inv2);
        }
    }
    __syncthreads();

    // ---- out = P . V ----
    {
        uint32_t pBase = (uint32_t)__cvta_generic_to_shared(
            &sh[(w*16 + (lane&15))*12 + (lane>>4)*4]);
        uint32_t vBase = (uint32_t)__cvta_generic_to_shared(
            &vt[0][((lane>>4) ? 8 : 0) + (lane&7)][((lane>>3)&1)*4]);
        float4 o[4];
        #pragma unroll
        for (int i = 0; i < 4; i++) o[i] = make_float4(0.f,0.f,0.f,0.f);
        #pragma unroll
        for (int s = 0; s < 4; s++) {
            uint32_t afr[4], bfr[2][4];
            ldmx4(afr, pBase + s*64*48);
            #pragma unroll
            for (int np = 0; np < 2; np++) ldmx4(bfr[np], vBase + s*32*48 + np*16*48);
            mma_bf16(o[0], afr, &bfr[0][0]);
            mma_bf16(o[1], afr, &bfr[0][2]);
            mma_bf16(o[2], afr, &bfr[1][0]);
            mma_bf16(o[3], afr, &bfr[1][2]);
        }
        __nv_bfloat16* ob = g_atth + ((size_t)win*Ln)*Cn + head*HDn;
        int i0 = w*16 + g;
        #pragma unroll
        for (int nt = 0; nt < 4; nt++) {
            int c = nt*8 + 2*t4;   // even
            if (i0 < Ln)
                *(uint32_t*)&ob[i0*Cn + c] = pack_bf16(o[nt].x, o[nt].y);
            if (i0 + 8 < Ln)
                *(uint32_t*)&ob[(i0+8)*Cn + c] = pack_bf16(o[nt].z, o[nt].w);
        }
    }
}

// ---------------- launch ----------------
extern "C" void kernel_launch(void* const* d_in, const int* in_sizes, int n_in,
                              void* d_out, int out_size) {
    const float* x       = (const float*)d_in[0];
    const float* ape_w   = (const float*)d_in[1];
    const float* ape_b   = (const float*)d_in[2];
    const float* norm1_w = (const float*)d_in[3];
    const float* norm1_b = (const float*)d_in[4];
    const float* qkv_w   = (const float*)d_in[5];
    const float* qkv_b   = (const float*)d_in[6];
    const float* scale   = (const float*)d_in[7];
    const float* rpb1_w  = (const float*)d_in[8];
    const float* rpb1_b  = (const float*)d_in[9];
    const float* rpb2_w  = (const float*)d_in[10];
    const float* rpb2_b  = (const float*)d_in[11];
    const float* proj_w  = (const float*)d_in[12];
    const float* proj_b  = (const float*)d_in[13];
    const float* norm2_w = (const float*)d_in[14];
    const float* norm2_b = (const float*)d_in[15];
    const float* fc1_w   = (const float*)d_in[16];
    const float* fc1_b   = (const float*)d_in[17];
    const float* fc2_w   = (const float*)d_in[18];
    const float* fc2_b   = (const float*)d_in[19];
    float* out = (float*)d_out;

    static int smem_set = 0;
    if (!smem_set) {
        cudaFuncSetAttribute(gemm_tc<0,256>,
            cudaFuncAttributeMaxDynamicSharedMemorySize, GSMEM_BYTES);
        cudaFuncSetAttribute(gemm_tc<1,256>,
            cudaFuncAttributeMaxDynamicSharedMemorySize, GSMEM_BYTES);
        cudaFuncSetAttribute(gemm_tc<2,256>,
            cudaFuncAttributeMaxDynamicSharedMemorySize, GSMEM_BYTES);
        cudaFuncSetAttribute(gemm_tc<3,1024>,
            cudaFuncAttributeMaxDynamicSharedMemorySize, GSMEM_BYTES);
        smem_set = 1;
    }

    convert_w_kernel<<<(W_TOT + 255)/256, 256>>>(qkv_w, proj_w, fc1_w, fc2_w);
    setup_table_kernel<<<169, 256>>>(rpb1_w, rpb1_b, rpb2_w, rpb2_b);
    setup_bias_kernel2<<<(NHn*Ln*Ln + 255)/256, 256>>>();
    ape_ln_kernel<<<Bn*Hn*7, 256>>>(x, ape_w, ape_b, norm1_w, norm1_b);
    gemm_tc<0, 256><<<dim3(NPIX/128, 768/128),  256, GSMEM_BYTES>>>(W_QKV, qkv_b, nullptr);
    attn_kernel<<<dim3(NWIN, NHn), 128>>>(scale);
    gemm_tc<1, 256><<<dim3(NPIX/128, 256/128),  256, GSMEM_BYTES>>>(W_PROJ, proj_b, nullptr);
    ln2_kernel<<<NPIX/8, 256>>>(norm2_w, norm2_b);
    gemm_tc<2, 256><<<dim3(NPIX/128, 1024/128), 256, GSMEM_BYTES>>>(W_FC1, fc1_b, nullptr);
    gemm_tc<3, 1024><<<dim3(NPIX/128, 256/128), 256, GSMEM_BYTES>>>(W_FC2, fc2_b, out);
}